// round 16
// baseline (speedup 1.0000x reference)
#include <cuda_runtime.h>
#include <cuda_fp16.h>
#include <math.h>
#include <stdint.h>

#define N_TOK 4096      // B*S
#define DDIM  1024      // D
#define FDIM  4096      // F
#define NEXP  8         // E
#define LN_EPS 1e-5f

#define BM 128
#define BN 128
#define BK 64                    // fp16 elements per K chunk (128 B rows)
#define ROWB 144                 // 128 B data + 16 B pad (conflict-free)
#define ATILE (128 * ROWB)       // 18432 B per operand tile
// Stage = 2 live tiles (36864 B) padded to 40960 so SMEM stays 122880 ->
// exactly 1 CTA/SM (R13-validated geometry; avoids ptxas 64-reg squeeze).
#define STAGEB 40960
#define NSTAGE 3
#define SMEM_BYTES (NSTAGE * STAGEB)  // 122880 B

#define W2_CHUNKS 4096           // (NEXP*DDIM*FDIM) / 8192

// ---- static device scratch (no runtime allocation allowed) ----
__device__ int   g_counts[NEXP];
__device__ int   g_ticket;                      // W2-convert work ticket
__device__ int   g_rows[NEXP * N_TOK];          // value = token*2 + slot
__device__ float g_slotw[2 * N_TOK];            // softmax weight per slot
__device__ __half g_X [N_TOK * DDIM];           // activations fp16
__device__ __half g_W1[NEXP * FDIM * DDIM];     // weights fp16
__device__ __half g_W2[NEXP * DDIM * FDIM];
__device__ __half g_H [(size_t)2 * N_TOK * FDIM]; // relu(x@W1^T+b1), fp16
__device__ __half g_Y [(size_t)2 * N_TOK * DDIM]; // H@W2^T+b2 (unweighted), fp16

// ============================ PTX helpers ============================
static __device__ __forceinline__ void cp16(uint32_t s, const void* g) {
    asm volatile("cp.async.cg.shared.global [%0], [%1], 16;" :: "r"(s), "l"(g));
}

#define LDSM4(r0, r1, r2, r3, addr)                                           \
    asm volatile("ldmatrix.sync.aligned.m8n8.x4.shared.b16 {%0,%1,%2,%3}, [%4];" \
                 : "=r"(r0), "=r"(r1), "=r"(r2), "=r"(r3) : "r"(addr))

// fp16 inputs, fp32 accumulators
#define MMAF32(d, a, b0, b1)                                                  \
    asm volatile("mma.sync.aligned.m16n8k16.row.col.f32.f16.f16.f32 "         \
                 "{%0,%1,%2,%3}, {%4,%5,%6,%7}, {%8,%9}, {%0,%1,%2,%3};"      \
                 : "+f"((d)[0]), "+f"((d)[1]), "+f"((d)[2]), "+f"((d)[3])     \
                 : "r"((a)[0]), "r"((a)[1]), "r"((a)[2]), "r"((a)[3]),        \
                   "r"(b0), "r"(b1))

// ============================ init ============================
__global__ void init_kernel() {
    if (threadIdx.x < NEXP) g_counts[threadIdx.x] = 0;
    if (threadIdx.x == NEXP) g_ticket = 0;
}

// ============================ prep: router + cvt(X) + cvt(W1) ============================
// blocks [0,512):      router, 8 tokens per block (one warp each)
// blocks [512,4608):   X  fp32->fp16, 1024 elements per block
// blocks [4608,37376): W1 fp32->fp16, 1024 elements per block
__global__ void prep_kernel(const float* __restrict__ tgt,
                            const float* __restrict__ Wr,
                            const float* __restrict__ br,
                            const float* __restrict__ W1) {
    int b = blockIdx.x;
    int tid = threadIdx.x;

    if (b >= 512) {
        const float* src;
        __half* dst;
        size_t i;
        if (b < 4608) { src = tgt; dst = g_X;  i = (size_t)(b - 512) * 1024 + tid * 4; }
        else          { src = W1;  dst = g_W1; i = (size_t)(b - 4608) * 1024 + tid * 4; }
        float4 v = *(const float4*)(src + i);
        __half2 a; a.x = __float2half_rn(v.x); a.y = __float2half_rn(v.y);
        __half2 c; c.x = __float2half_rn(v.z); c.y = __float2half_rn(v.w);
        *(__half2*)(dst + i)     = a;
        *(__half2*)(dst + i + 2) = c;
        return;
    }

    // ---- router ----
    int token = b * 8 + (tid >> 5);
    int lane  = tid & 31;

    const float* x = tgt + (size_t)token * DDIM;
    float xr[32];
#pragma unroll
    for (int i = 0; i < 32; i++) xr[i] = x[lane + 32 * i];

    float logits[NEXP];
#pragma unroll
    for (int e = 0; e < NEXP; e++) {
        const float* w = Wr + e * DDIM;
        float s = 0.f;
#pragma unroll
        for (int i = 0; i < 32; i++) s += xr[i] * w[lane + 32 * i];
#pragma unroll
        for (int o = 16; o > 0; o >>= 1) s += __shfl_xor_sync(0xffffffffu, s, o);
        logits[e] = s + br[e];
    }

    if (lane == 0) {
        int i0 = 0; float v0 = logits[0];
#pragma unroll
        for (int e = 1; e < NEXP; e++) if (logits[e] > v0) { v0 = logits[e]; i0 = e; }
        int i1 = -1; float v1 = -INFINITY;
#pragma unroll
        for (int e = 0; e < NEXP; e++) if (e != i0 && logits[e] > v1) { v1 = logits[e]; i1 = e; }
        float e1  = expf(v1 - v0);
        float inv = 1.f / (1.f + e1);
        g_slotw[2 * token]     = inv;
        g_slotw[2 * token + 1] = e1 * inv;
        int p0 = atomicAdd(&g_counts[i0], 1); g_rows[i0 * N_TOK + p0] = 2 * token;
        int p1 = atomicAdd(&g_counts[i1], 1); g_rows[i1 * N_TOK + p1] = 2 * token + 1;
    }
}

// ============================ mma.sync grouped GEMM ============================
// C[m][n] = sum_k A[m][k]*B[n][k], fp16 inputs, fp32 accumulate.
// 512 thr = 16 warps (4 M x 4 N), warp tile 32x32, block tile 128x128, BK=64.
// 3-stage cp.async ring, ONE __syncthreads per K-chunk (32 MMAs between syncs).
// GEMM1 idle blocks (mt beyond expert count) convert W2 fp32->fp16 instead.
__global__ void __launch_bounds__(512, 1)
mma_gemm_kernel(int is_gemm1, int Ndim, int Kdim,
                const float* __restrict__ bias,
                const float* __restrict__ w2src) {
    extern __shared__ __align__(128) char smem[];
    uint32_t sb = (uint32_t)__cvta_generic_to_shared(smem);

    int e  = blockIdx.z;
    int nt = blockIdx.y;
    int mt = blockIdx.x;     // mt fastest -> concurrent blocks share weight tile (L2)
    int cnt = g_counts[e];
    int tid = threadIdx.x;

    if (mt * BM >= cnt) {
        // Idle block: in GEMM1, convert W2 chunks (overlapped with tensor work;
        // kernel boundary orders completion before GEMM2 reads g_W2).
        if (is_gemm1) {
            int* s_chunk = (int*)smem;
            while (true) {
                if (tid == 0) *s_chunk = atomicAdd(&g_ticket, 1);
                __syncthreads();
                int c = *s_chunk;
                __syncthreads();
                if (c >= W2_CHUNKS) break;
                size_t base = (size_t)c * 8192;
#pragma unroll
                for (int j = 0; j < 4; j++) {
                    size_t idx = base + ((size_t)j * 512 + tid) * 4;
                    float4 v = *(const float4*)(w2src + idx);
                    __half2 a; a.x = __float2half_rn(v.x); a.y = __float2half_rn(v.y);
                    __half2 d; d.x = __float2half_rn(v.z); d.y = __float2half_rn(v.w);
                    *(__half2*)(g_W2 + idx)     = a;
                    *(__half2*)(g_W2 + idx + 2) = d;
                }
            }
        }
        return;
    }

    const int* erows = g_rows + e * N_TOK;
    const __half *Ab, *Wb;
    if (is_gemm1) { Ab = g_X; Wb = g_W1; }
    else          { Ab = g_H; Wb = g_W2; }

    // ---- global->smem geometry: thread -> (row = tid>>2, 32B quarter = tid&3) ----
    int lrow = tid >> 2;
    int q    = tid & 3;
    int kb   = q * 16;                       // element offset of this thread's 32B
    int mr_l = mt * BM + lrow; if (mr_l > cnt - 1) mr_l = cnt - 1;
    int arow = erows[mr_l]; if (is_gemm1) arow >>= 1;
    const __half* apx = Ab + (size_t)arow * Kdim + kb;
    const __half* bpw = Wb + ((size_t)e * Ndim + nt * BN + lrow) * Kdim + kb;
    uint32_t dst = (uint32_t)lrow * ROWB + q * 32;

    // ---- fragment (ldmatrix) geometry ----
    int lane = tid & 31, wid = tid >> 5;
    int wm = wid & 3, wn = wid >> 2;         // warp tile origin (wm*32, wn*32)
    uint32_t afa = (uint32_t)(wm * 32 + (lane & 15)) * ROWB + (lane >> 4) * 16;
    uint32_t bfa = (uint32_t)(wn * 32 + (lane & 15)) * ROWB + (lane >> 4) * 16;

    float accM[2][4][4];
#pragma unroll
    for (int mi = 0; mi < 2; mi++)
#pragma unroll
        for (int ni = 0; ni < 4; ni++)
#pragma unroll
            for (int r = 0; r < 4; r++) accM[mi][ni][r] = 0.f;

    auto issue = [&](int i) {
        uint32_t d = sb + (uint32_t)(i % NSTAGE) * STAGEB + dst;
        size_t ko = (size_t)i * BK;
        cp16(d,               apx + ko);
        cp16(d + 16,          apx + ko + 8);
        cp16(d + ATILE,       bpw + ko);
        cp16(d + ATILE + 16,  bpw + ko + 8);
        asm volatile("cp.async.commit_group;" ::: "memory");
    };

    int nch = Kdim / BK;
    issue(0);
    if (nch > 1) issue(1);
    for (int i = 0; i < nch; i++) {
        if (i + 1 < nch) {
            asm volatile("cp.async.wait_group 1;" ::: "memory");
        } else {
            asm volatile("cp.async.wait_group 0;" ::: "memory");
        }
        __syncthreads();   // chunk i visible; stage (i+2)%3 free for reuse
        if (i + 2 < nch) issue(i + 2);

        uint32_t bb = sb + (uint32_t)(i % NSTAGE) * STAGEB;
#pragma unroll
        for (int s = 0; s < 4; s++) {        // four k16 steps per 64-wide chunk
            uint32_t aA = bb + afa + s * 32;           // A
            uint32_t aB = bb + ATILE + bfa + s * 32;   // B (weights)
            uint32_t af[2][4], bf[2][4];

#pragma unroll
            for (int mi = 0; mi < 2; mi++)
                LDSM4(af[mi][0], af[mi][1], af[mi][2], af[mi][3], aA + mi * 16 * ROWB);
#pragma unroll
            for (int nj = 0; nj < 2; nj++)
                LDSM4(bf[nj][0], bf[nj][1], bf[nj][2], bf[nj][3], aB + nj * 16 * ROWB);

#pragma unroll
            for (int mi = 0; mi < 2; mi++)
#pragma unroll
                for (int ni = 0; ni < 4; ni++)
                    MMAF32(accM[mi][ni], af[mi],
                           bf[ni >> 1][ni & 1], bf[ni >> 1][(ni & 1) + 2]);
        }
    }

    // ---- epilogue ----
    int tg = lane >> 2, tc = (lane & 3) * 2;
    const float* bbias = bias + e * Ndim + nt * BN;
    float bias_r[8];
#pragma unroll
    for (int ni = 0; ni < 4; ni++) {
        int c = wn * 32 + ni * 8 + tc;
        bias_r[2 * ni]     = __ldg(bbias + c);
        bias_r[2 * ni + 1] = __ldg(bbias + c + 1);
    }
#pragma unroll
    for (int mi = 0; mi < 2; mi++) {
#pragma unroll
        for (int half = 0; half < 2; half++) {
            int r = wm * 32 + mi * 16 + tg + half * 8;
            int mr = mt * BM + r;
            if (mr < cnt) {
                int orow = erows[mr];
#pragma unroll
                for (int ni = 0; ni < 4; ni++) {
                    int c = wn * 32 + ni * 8 + tc;
                    float v0 = accM[mi][ni][half * 2]     + bias_r[2 * ni];
                    float v1 = accM[mi][ni][half * 2 + 1] + bias_r[2 * ni + 1];
                    int n = nt * BN + c;
                    if (is_gemm1) {
                        v0 = fmaxf(v0, 0.f); v1 = fmaxf(v1, 0.f);
                        __half2 hh;
                        hh.x = __float2half_rn(v0);
                        hh.y = __float2half_rn(v1);
                        *(__half2*)(g_H + (size_t)orow * FDIM + n) = hh;
                    } else {
                        __half2 hh;
                        hh.x = __float2half_rn(v0);
                        hh.y = __float2half_rn(v1);
                        *(__half2*)(g_Y + (size_t)orow * DDIM + n) = hh;
                    }
                }
            }
        }
    }
}

// ============================ LN ============================
__global__ void ln_kernel(const float* __restrict__ tgt,
                          const float* __restrict__ gamma,
                          const float* __restrict__ beta,
                          float* __restrict__ out) {
    int token = blockIdx.x;
    int tid = threadIdx.x;
    __shared__ float red[8];

    float w0 = g_slotw[2 * token], w1 = g_slotw[2 * token + 1];
    const float*  x  = tgt + (size_t)token * DDIM;
    const __half* y0 = g_Y + (size_t)(2 * token) * DDIM;
    const __half* y1 = y0 + DDIM;

    int d0 = tid * 4;
    float4 xv = *(const float4*)(x + d0);
    __half2 p0 = *(const __half2*)(y0 + d0);
    __half2 p1 = *(const __half2*)(y0 + d0 + 2);
    __half2 q0 = *(const __half2*)(y1 + d0);
    __half2 q1 = *(const __half2*)(y1 + d0 + 2);

    float v[4];
    v[0] = xv.x + w0 * __low2float(p0)  + w1 * __low2float(q0);
    v[1] = xv.y + w0 * __high2float(p0) + w1 * __high2float(q0);
    v[2] = xv.z + w0 * __low2float(p1)  + w1 * __low2float(q1);
    v[3] = xv.w + w0 * __high2float(p1) + w1 * __high2float(q1);

    float s = v[0] + v[1] + v[2] + v[3];
#pragma unroll
    for (int o = 16; o > 0; o >>= 1) s += __shfl_xor_sync(0xffffffffu, s, o);
    if ((tid & 31) == 0) red[tid >> 5] = s;
    __syncthreads();
    float mu = (red[0] + red[1] + red[2] + red[3] + red[4] + red[5] + red[6] + red[7]) * (1.f / DDIM);

    float sq = 0.f;
#pragma unroll
    for (int i = 0; i < 4; i++) { float dv = v[i] - mu; sq += dv * dv; }
#pragma unroll
    for (int o = 16; o > 0; o >>= 1) sq += __shfl_xor_sync(0xffffffffu, sq, o);
    __syncthreads();
    if ((tid & 31) == 0) red[tid >> 5] = sq;
    __syncthreads();
    float var = (red[0] + red[1] + red[2] + red[3] + red[4] + red[5] + red[6] + red[7]) * (1.f / DDIM);
    float inv = rsqrtf(var + LN_EPS);

    float4 gv = *(const float4*)(gamma + d0);
    float4 bv = *(const float4*)(beta + d0);
    float4 ov;
    ov.x = (v[0] - mu) * inv * gv.x + bv.x;
    ov.y = (v[1] - mu) * inv * gv.y + bv.y;
    ov.z = (v[2] - mu) * inv * gv.z + bv.z;
    ov.w = (v[3] - mu) * inv * gv.w + bv.w;
    *(float4*)(out + (size_t)token * DDIM + d0) = ov;
}

// ============================ launch ============================
extern "C" void kernel_launch(void* const* d_in, const int* in_sizes, int n_in,
                              void* d_out, int out_size) {
    const float* tgt   = (const float*)d_in[0];
    const float* Wr    = (const float*)d_in[1];
    const float* br    = (const float*)d_in[2];
    const float* W1    = (const float*)d_in[3];
    const float* b1    = (const float*)d_in[4];
    const float* W2    = (const float*)d_in[5];
    const float* b2    = (const float*)d_in[6];
    const float* gamma = (const float*)d_in[7];
    const float* beta  = (const float*)d_in[8];
    float* out = (float*)d_out;

    cudaFuncSetAttribute(mma_gemm_kernel,
                         cudaFuncAttributeMaxDynamicSharedMemorySize, SMEM_BYTES);

    init_kernel<<<1, 32>>>();

    // router + cvt(X) + cvt(W1) fused; W2 converts inside GEMM1's idle blocks
    prep_kernel<<<512 + 4096 + 32768, 256>>>(tgt, Wr, br, W1);

    // GEMM1: X @ W1^T -> H (bias+relu, fp16); idle blocks convert W2
    dim3 g1(N_TOK / BM, FDIM / BN, NEXP);   // x=mt, y=nt, z=e
    mma_gemm_kernel<<<g1, 512, SMEM_BYTES>>>(1, FDIM, DDIM, b1, W2);

    // GEMM2: H @ W2^T -> Y fp16 (bias)
    dim3 g2(N_TOK / BM, DDIM / BN, NEXP);   // (32, 8, 8)
    mma_gemm_kernel<<<g2, 512, SMEM_BYTES>>>(0, DDIM, FDIM, b2, W2);

    ln_kernel<<<N_TOK, 256>>>(tgt, gamma, beta, out);
}

// round 17
// speedup vs baseline: 1.4432x; 1.4432x over previous
#include <cuda_runtime.h>
#include <cuda_fp16.h>
#include <math.h>
#include <stdint.h>

#define N_TOK 4096      // B*S
#define DDIM  1024      // D
#define FDIM  4096      // F
#define NEXP  8         // E
#define LN_EPS 1e-5f

#define BM 128
#define BN 128
#define BK 32
#define ROWB 80                  // smem bytes per row: 32 fp16 + 8 pad
#define ATILE (128 * ROWB)       // 10240 B per operand tile
// Stage = 2 live tiles (20480 B) padded to 40960 so SMEM stays 122880 ->
// exactly 1 CTA/SM (R13/R15-validated geometry; avoids ptxas 64-reg squeeze).
#define STAGEB 40960
#define NSTAGE 3
#define SMEM_BYTES (NSTAGE * STAGEB)  // 122880 B

#define W2_CHUNKS 4096           // (NEXP*DDIM*FDIM) / 8192

// ---- static device scratch (no runtime allocation allowed) ----
__device__ int   g_counts[NEXP];
__device__ int   g_ticket;                      // W2-convert work ticket
__device__ int   g_rows[NEXP * N_TOK];          // value = token*2 + slot
__device__ float g_slotw[2 * N_TOK];            // softmax weight per slot
__device__ __half g_X [N_TOK * DDIM];           // activations fp16
__device__ __half g_W1[NEXP * FDIM * DDIM];     // weights fp16
__device__ __half g_W2[NEXP * DDIM * FDIM];
__device__ __half g_H [(size_t)2 * N_TOK * FDIM]; // relu(x@W1^T+b1), fp16
__device__ float g_Y[(size_t)2 * N_TOK * DDIM]; // H@W2^T+b2 (unweighted), fp32

// ============================ PTX helpers ============================
static __device__ __forceinline__ void cp16(uint32_t s, const void* g) {
    asm volatile("cp.async.cg.shared.global [%0], [%1], 16;" :: "r"(s), "l"(g));
}

#define LDSM4(r0, r1, r2, r3, addr)                                           \
    asm volatile("ldmatrix.sync.aligned.m8n8.x4.shared.b16 {%0,%1,%2,%3}, [%4];" \
                 : "=r"(r0), "=r"(r1), "=r"(r2), "=r"(r3) : "r"(addr))

// fp16 inputs, fp32 accumulators
#define MMAF32(d, a, b0, b1)                                                  \
    asm volatile("mma.sync.aligned.m16n8k16.row.col.f32.f16.f16.f32 "         \
                 "{%0,%1,%2,%3}, {%4,%5,%6,%7}, {%8,%9}, {%0,%1,%2,%3};"      \
                 : "+f"((d)[0]), "+f"((d)[1]), "+f"((d)[2]), "+f"((d)[3])     \
                 : "r"((a)[0]), "r"((a)[1]), "r"((a)[2]), "r"((a)[3]),        \
                   "r"(b0), "r"(b1))

// ============================ init ============================
__global__ void init_kernel() {
    if (threadIdx.x < NEXP) g_counts[threadIdx.x] = 0;
    if (threadIdx.x == NEXP) g_ticket = 0;
}

// ============================ prep: router + cvt(X) + cvt(W1) ============================
// blocks [0,512):      router, 8 tokens per block (one warp each)
// blocks [512,4608):   X  fp32->fp16, 1024 elements per block
// blocks [4608,37376): W1 fp32->fp16, 1024 elements per block
__global__ void prep_kernel(const float* __restrict__ tgt,
                            const float* __restrict__ Wr,
                            const float* __restrict__ br,
                            const float* __restrict__ W1) {
    int b = blockIdx.x;
    int tid = threadIdx.x;

    if (b >= 512) {
        const float* src;
        __half* dst;
        size_t i;
        if (b < 4608) { src = tgt; dst = g_X;  i = (size_t)(b - 512) * 1024 + tid * 4; }
        else          { src = W1;  dst = g_W1; i = (size_t)(b - 4608) * 1024 + tid * 4; }
        float4 v = *(const float4*)(src + i);
        __half2 a; a.x = __float2half_rn(v.x); a.y = __float2half_rn(v.y);
        __half2 c; c.x = __float2half_rn(v.z); c.y = __float2half_rn(v.w);
        *(__half2*)(dst + i)     = a;
        *(__half2*)(dst + i + 2) = c;
        return;
    }

    // ---- router ----
    int token = b * 8 + (tid >> 5);
    int lane  = tid & 31;

    const float* x = tgt + (size_t)token * DDIM;
    float xr[32];
#pragma unroll
    for (int i = 0; i < 32; i++) xr[i] = x[lane + 32 * i];

    float logits[NEXP];
#pragma unroll
    for (int e = 0; e < NEXP; e++) {
        const float* w = Wr + e * DDIM;
        float s = 0.f;
#pragma unroll
        for (int i = 0; i < 32; i++) s += xr[i] * w[lane + 32 * i];
#pragma unroll
        for (int o = 16; o > 0; o >>= 1) s += __shfl_xor_sync(0xffffffffu, s, o);
        logits[e] = s + br[e];
    }

    if (lane == 0) {
        int i0 = 0; float v0 = logits[0];
#pragma unroll
        for (int e = 1; e < NEXP; e++) if (logits[e] > v0) { v0 = logits[e]; i0 = e; }
        int i1 = -1; float v1 = -INFINITY;
#pragma unroll
        for (int e = 0; e < NEXP; e++) if (e != i0 && logits[e] > v1) { v1 = logits[e]; i1 = e; }
        float e1  = expf(v1 - v0);
        float inv = 1.f / (1.f + e1);
        g_slotw[2 * token]     = inv;
        g_slotw[2 * token + 1] = e1 * inv;
        int p0 = atomicAdd(&g_counts[i0], 1); g_rows[i0 * N_TOK + p0] = 2 * token;
        int p1 = atomicAdd(&g_counts[i1], 1); g_rows[i1 * N_TOK + p1] = 2 * token + 1;
    }
}

// ============================ mma.sync grouped GEMM ============================
// C[m][n] = sum_k A[m][k]*B[n][k], fp16 inputs, fp32 accumulate.
// 512 thr = 16 warps (4 M x 4 N), warp tile 32x32, block tile 128x128, BK=32.
// 3-stage cp.async ring, ONE __syncthreads per K-chunk.  (R15 mainloop, unchanged.)
// GEMM1 idle blocks (mt beyond expert count) convert W2 fp32->fp16 instead.
__global__ void __launch_bounds__(512, 1)
mma_gemm_kernel(int is_gemm1, int Ndim, int Kdim,
                const float* __restrict__ bias,
                const float* __restrict__ w2src) {
    extern __shared__ __align__(128) char smem[];
    uint32_t sb = (uint32_t)__cvta_generic_to_shared(smem);

    int e  = blockIdx.z;
    int nt = blockIdx.y;
    int mt = blockIdx.x;     // mt fastest -> concurrent blocks share weight tile (L2)
    int cnt = g_counts[e];
    int tid = threadIdx.x;

    if (mt * BM >= cnt) {
        // Idle block: during GEMM1, convert W2 chunks (hidden under tensor work;
        // the kernel boundary orders completion before GEMM2 reads g_W2).
        if (is_gemm1) {
            int* s_chunk = (int*)smem;
            while (true) {
                if (tid == 0) *s_chunk = atomicAdd(&g_ticket, 1);
                __syncthreads();
                int c = *s_chunk;
                __syncthreads();
                if (c >= W2_CHUNKS) break;
                size_t base = (size_t)c * 8192;
#pragma unroll
                for (int j = 0; j < 4; j++) {
                    size_t idx = base + ((size_t)j * 512 + tid) * 4;
                    float4 v = *(const float4*)(w2src + idx);
                    __half2 a; a.x = __float2half_rn(v.x); a.y = __float2half_rn(v.y);
                    __half2 d; d.x = __float2half_rn(v.z); d.y = __float2half_rn(v.w);
                    *(__half2*)(g_W2 + idx)     = a;
                    *(__half2*)(g_W2 + idx + 2) = d;
                }
            }
        }
        return;
    }

    const int* erows = g_rows + e * N_TOK;
    const __half *Ab, *Wb;
    if (is_gemm1) { Ab = g_X; Wb = g_W1; }
    else          { Ab = g_H; Wb = g_W2; }

    // ---- global->smem geometry: thread -> (row = tid>>2, 16B seg = tid&3) ----
    int lrow = tid >> 2;
    int seg  = tid & 3;
    int kb   = seg * 8;                      // element offset of this thread's 16B
    int mr_l = mt * BM + lrow; if (mr_l > cnt - 1) mr_l = cnt - 1;
    int arow = erows[mr_l]; if (is_gemm1) arow >>= 1;
    const __half* apx = Ab + (size_t)arow * Kdim + kb;
    const __half* bpw = Wb + ((size_t)e * Ndim + nt * BN + lrow) * Kdim + kb;
    uint32_t dst = (uint32_t)lrow * ROWB + seg * 16;

    // ---- fragment (ldmatrix) geometry ----
    int lane = tid & 31, wid = tid >> 5;
    int wm = wid & 3, wn = wid >> 2;         // warp tile origin (wm*32, wn*32)
    uint32_t afa = (uint32_t)(wm * 32 + (lane & 15)) * ROWB + (lane >> 4) * 16;
    uint32_t bfa = (uint32_t)(wn * 32 + (lane & 15)) * ROWB + (lane >> 4) * 16;

    float accM[2][4][4];
#pragma unroll
    for (int mi = 0; mi < 2; mi++)
#pragma unroll
        for (int ni = 0; ni < 4; ni++)
#pragma unroll
            for (int r = 0; r < 4; r++) accM[mi][ni][r] = 0.f;

    auto issue = [&](int i) {
        uint32_t d = sb + (uint32_t)(i % NSTAGE) * STAGEB + dst;
        size_t ko = (size_t)i * BK;
        cp16(d,          apx + ko);
        cp16(d + ATILE,  bpw + ko);
        asm volatile("cp.async.commit_group;" ::: "memory");
    };

    int nch = Kdim / BK;
    issue(0);
    if (nch > 1) issue(1);
    for (int i = 0; i < nch; i++) {
        if (i + 1 < nch) {
            asm volatile("cp.async.wait_group 1;" ::: "memory");
        } else {
            asm volatile("cp.async.wait_group 0;" ::: "memory");
        }
        __syncthreads();   // chunk i visible; stage (i+2)%3 free for reuse
        if (i + 2 < nch) issue(i + 2);

        uint32_t bb = sb + (uint32_t)(i % NSTAGE) * STAGEB;
#pragma unroll
        for (int s = 0; s < 2; s++) {        // two k16 steps per chunk
            uint32_t aA = bb + afa + s * 32;           // A
            uint32_t aB = bb + ATILE + bfa + s * 32;   // B (weights)
            uint32_t af[2][4], bf[2][4];

#pragma unroll
            for (int mi = 0; mi < 2; mi++)
                LDSM4(af[mi][0], af[mi][1], af[mi][2], af[mi][3], aA + mi * 16 * ROWB);
#pragma unroll
            for (int nj = 0; nj < 2; nj++)
                LDSM4(bf[nj][0], bf[nj][1], bf[nj][2], bf[nj][3], aB + nj * 16 * ROWB);

#pragma unroll
            for (int mi = 0; mi < 2; mi++)
#pragma unroll
                for (int ni = 0; ni < 4; ni++)
                    MMAF32(accM[mi][ni], af[mi],
                           bf[ni >> 1][ni & 1], bf[ni >> 1][(ni & 1) + 2]);
        }
    }

    // ---- epilogue ----
    int tg = lane >> 2, tc = (lane & 3) * 2;
    const float* bbias = bias + e * Ndim + nt * BN;
    float bias_r[8];
#pragma unroll
    for (int ni = 0; ni < 4; ni++) {
        int c = wn * 32 + ni * 8 + tc;
        bias_r[2 * ni]     = __ldg(bbias + c);
        bias_r[2 * ni + 1] = __ldg(bbias + c + 1);
    }
#pragma unroll
    for (int mi = 0; mi < 2; mi++) {
#pragma unroll
        for (int half = 0; half < 2; half++) {
            int r = wm * 32 + mi * 16 + tg + half * 8;
            int mr = mt * BM + r;
            if (mr < cnt) {
                int orow = erows[mr];
#pragma unroll
                for (int ni = 0; ni < 4; ni++) {
                    int c = wn * 32 + ni * 8 + tc;
                    float v0 = accM[mi][ni][half * 2]     + bias_r[2 * ni];
                    float v1 = accM[mi][ni][half * 2 + 1] + bias_r[2 * ni + 1];
                    int n = nt * BN + c;
                    if (is_gemm1) {
                        v0 = fmaxf(v0, 0.f); v1 = fmaxf(v1, 0.f);
                        __half2 hh;
                        hh.x = __float2half_rn(v0);
                        hh.y = __float2half_rn(v1);
                        *(__half2*)(g_H + (size_t)orow * FDIM + n) = hh;
                    } else {
                        float2 t; t.x = v0; t.y = v1;
                        *(float2*)(g_Y + (size_t)orow * DDIM + n) = t;
                    }
                }
            }
        }
    }
}

// ============================ LN ============================
__global__ void ln_kernel(const float* __restrict__ tgt,
                          const float* __restrict__ gamma,
                          const float* __restrict__ beta,
                          float* __restrict__ out) {
    int token = blockIdx.x;
    int tid = threadIdx.x;
    __shared__ float red[8];

    float w0 = g_slotw[2 * token], w1 = g_slotw[2 * token + 1];
    const float* x  = tgt + (size_t)token * DDIM;
    const float* y0 = g_Y + (size_t)(2 * token) * DDIM;
    const float* y1 = y0 + DDIM;

    float v[4];
    float s = 0.f;
#pragma unroll
    for (int i = 0; i < 4; i++) {
        int d = tid + 256 * i;
        v[i] = x[d] + w0 * y0[d] + w1 * y1[d];
        s += v[i];
    }
#pragma unroll
    for (int o = 16; o > 0; o >>= 1) s += __shfl_xor_sync(0xffffffffu, s, o);
    if ((tid & 31) == 0) red[tid >> 5] = s;
    __syncthreads();
    float mu = (red[0] + red[1] + red[2] + red[3] + red[4] + red[5] + red[6] + red[7]) * (1.f / DDIM);

    float sq = 0.f;
#pragma unroll
    for (int i = 0; i < 4; i++) { float dv = v[i] - mu; sq += dv * dv; }
#pragma unroll
    for (int o = 16; o > 0; o >>= 1) sq += __shfl_xor_sync(0xffffffffu, sq, o);
    __syncthreads();
    if ((tid & 31) == 0) red[tid >> 5] = sq;
    __syncthreads();
    float var = (red[0] + red[1] + red[2] + red[3] + red[4] + red[5] + red[6] + red[7]) * (1.f / DDIM);
    float inv = rsqrtf(var + LN_EPS);

#pragma unroll
    for (int i = 0; i < 4; i++) {
        int d = tid + 256 * i;
        out[(size_t)token * DDIM + d] = (v[i] - mu) * inv * gamma[d] + beta[d];
    }
}

// ============================ launch ============================
extern "C" void kernel_launch(void* const* d_in, const int* in_sizes, int n_in,
                              void* d_out, int out_size) {
    const float* tgt   = (const float*)d_in[0];
    const float* Wr    = (const float*)d_in[1];
    const float* br    = (const float*)d_in[2];
    const float* W1    = (const float*)d_in[3];
    const float* b1    = (const float*)d_in[4];
    const float* W2    = (const float*)d_in[5];
    const float* b2    = (const float*)d_in[6];
    const float* gamma = (const float*)d_in[7];
    const float* beta  = (const float*)d_in[8];
    float* out = (float*)d_out;

    cudaFuncSetAttribute(mma_gemm_kernel,
                         cudaFuncAttributeMaxDynamicSharedMemorySize, SMEM_BYTES);

    init_kernel<<<1, 32>>>();

    // router + cvt(X) + cvt(W1) fused; W2 converts inside GEMM1's idle blocks
    prep_kernel<<<512 + 4096 + 32768, 256>>>(tgt, Wr, br, W1);

    // GEMM1: X @ W1^T -> H (bias+relu, fp16); idle blocks convert W2
    dim3 g1(N_TOK / BM, FDIM / BN, NEXP);   // x=mt, y=nt, z=e
    mma_gemm_kernel<<<g1, 512, SMEM_BYTES>>>(1, FDIM, DDIM, b1, W2);

    // GEMM2: H @ W2^T -> Y fp32 (bias)
    dim3 g2(N_TOK / BM, DDIM / BN, NEXP);   // (32, 8, 8)
    mma_gemm_kernel<<<g2, 512, SMEM_BYTES>>>(0, DDIM, FDIM, b2, W2);

    ln_kernel<<<N_TOK, 256>>>(tgt, gamma, beta, out);
}